// round 2
// baseline (speedup 1.0000x reference)
#include <cuda_runtime.h>
#include <math.h>
#include <math_constants.h>

#define N_NODES 50000
#define N_EDGES 1000000
#define F_IN    30
#define C       64
#define EDIM    11
#define G_GR    1024
#define D_OUT   256
#define NLAYERS 4

// ---------------- device scratch (static, allocation-free) ----------------
__device__ float    g_feat[N_NODES * C];     // layer input / aggregated output
__device__ float    g_hw[N_NODES * C];       // h = x @ W
__device__ float    g_res[N_NODES * C];      // x @ Wres + b
__device__ float    g_hs[N_NODES];
__device__ float    g_hd[N_NODES];
__device__ int      g_rowptr[N_NODES + 1];
__device__ int      g_cnt[N_NODES];
__device__ int      g_csr_src[N_EDGES];
__device__ int      g_perm[N_EDGES];
__device__ float    g_et[NLAYERS * N_EDGES]; // per-layer edge term, CSR order
__device__ float    g_aeff[NLAYERS * EDIM];  // We @ ae per layer
__device__ unsigned g_gmax[G_GR * C];
__device__ float    g_gsum[G_GR * C];
__device__ int      g_gcnt[G_GR];

// monotone float<->uint encoding for atomicMax on floats
__device__ __forceinline__ unsigned fenc(float f) {
    unsigned u = __float_as_uint(f);
    return (u & 0x80000000u) ? ~u : (u | 0x80000000u);
}
__device__ __forceinline__ float fdec(unsigned u) {
    return (u & 0x80000000u) ? __uint_as_float(u ^ 0x80000000u)
                             : __uint_as_float(~u);
}

// ---------------- init: counters, pool accumulators, aeff -----------------
__global__ void k_init(const float* __restrict__ We0, const float* __restrict__ ae0,
                       const float* __restrict__ We,  const float* __restrict__ ae) {
    int i = blockIdx.x * blockDim.x + threadIdx.x;
    if (i < N_NODES) g_cnt[i] = 0;
    if (i < G_GR * C) { g_gmax[i] = 0u; g_gsum[i] = 0.0f; }
    if (i < G_GR) g_gcnt[i] = 0;
    if (i < NLAYERS * EDIM) {
        int l = i / EDIM, d = i % EDIM;
        const float* we = (l == 0) ? We0 : (We + (size_t)(l - 1) * EDIM * C);
        const float* av = (l == 0) ? ae0 : (ae + (size_t)(l - 1) * C);
        float s = 0.0f;
        #pragma unroll
        for (int c = 0; c < C; c++) s = fmaf(we[d * C + c], av[c], s);
        g_aeff[i] = s;
    }
}

// ---------------- CSR build ----------------
__global__ void k_hist(const int* __restrict__ edge_index) {
    int e = blockIdx.x * blockDim.x + threadIdx.x;
    if (e >= N_EDGES) return;
    int d = edge_index[N_EDGES + e];
    atomicAdd(&g_cnt[d], 1);
}

__global__ void k_scan() {
    __shared__ int wsum[32];
    const int T = 1024;
    int tid = threadIdx.x, lane = tid & 31, wid = tid >> 5;
    int chunk = (N_NODES + T - 1) / T;
    int beg = tid * chunk; if (beg > N_NODES) beg = N_NODES;
    int end = beg + chunk; if (end > N_NODES) end = N_NODES;
    int s = 0;
    for (int i = beg; i < end; i++) s += g_cnt[i];
    int v = s;
    #pragma unroll
    for (int o = 1; o < 32; o <<= 1) {
        int t = __shfl_up_sync(0xffffffffu, v, o);
        if (lane >= o) v += t;
    }
    if (lane == 31) wsum[wid] = v;
    __syncthreads();
    if (wid == 0) {
        int w = wsum[lane];
        #pragma unroll
        for (int o = 1; o < 32; o <<= 1) {
            int t = __shfl_up_sync(0xffffffffu, w, o);
            if (lane >= o) w += t;
        }
        wsum[lane] = w;
    }
    __syncthreads();
    int excl = (v - s) + ((wid > 0) ? wsum[wid - 1] : 0);
    int run = excl;
    for (int i = beg; i < end; i++) {
        int c = g_cnt[i];
        g_rowptr[i] = run;
        run += c;
        g_cnt[i] = 0;
    }
    if (tid == T - 1) g_rowptr[N_NODES] = run;
}

__global__ void k_scatter(const int* __restrict__ edge_index) {
    int e = blockIdx.x * blockDim.x + threadIdx.x;
    if (e >= N_EDGES) return;
    int s = edge_index[e];
    int d = edge_index[N_EDGES + e];
    int pos = g_rowptr[d] + atomicAdd(&g_cnt[d], 1);
    g_csr_src[pos] = s;
    g_perm[pos] = e;
}

// per-layer edge term et = edge_attr . (We@ae), written in CSR order
__global__ void k_et(const float* __restrict__ edge_attr) {
    int pos = blockIdx.x * blockDim.x + threadIdx.x;
    if (pos >= N_EDGES) return;
    int e = g_perm[pos];
    float ea[EDIM];
    #pragma unroll
    for (int j = 0; j < EDIM; j++) ea[j] = edge_attr[(size_t)e * EDIM + j];
    #pragma unroll
    for (int l = 0; l < NLAYERS; l++) {
        float s = 0.0f;
        #pragma unroll
        for (int j = 0; j < EDIM; j++) s = fmaf(ea[j], g_aeff[l * EDIM + j], s);
        g_et[(size_t)l * N_EDGES + pos] = s;
    }
}

// ---------------- fused node GEMM: h, res, hs, hd ----------------
template <int F, bool FIRST>
__global__ void k_gemm(const float* __restrict__ xin, const float* __restrict__ W,
                       const float* __restrict__ Wres, const float* __restrict__ asrcv,
                       const float* __restrict__ adstv, const float* __restrict__ bv) {
    __shared__ float Ws[F * C];
    __shared__ float Wr[F * C];
    __shared__ float as_[C], ad_[C], bs_[C];
    int tid = threadIdx.x;
    for (int i = tid; i < F * C; i += 256) { Ws[i] = W[i]; Wr[i] = Wres[i]; }
    if (tid < C) { as_[tid] = asrcv[tid]; ad_[tid] = adstv[tid]; bs_[tid] = bv[tid]; }
    __syncthreads();
    int lane = tid & 31, wid = tid >> 5;
    int row = blockIdx.x * 8 + wid;
    if (row >= N_NODES) return;
    const float* xr = FIRST ? (xin + (size_t)row * F) : (g_feat + (size_t)row * F);
    float a0 = 0, a1 = 0, r0 = 0, r1 = 0;
    #pragma unroll
    for (int k = 0; k < F; k++) {
        float xv = xr[k];
        a0 = fmaf(xv, Ws[k * C + lane], a0);
        a1 = fmaf(xv, Ws[k * C + lane + 32], a1);
        r0 = fmaf(xv, Wr[k * C + lane], r0);
        r1 = fmaf(xv, Wr[k * C + lane + 32], r1);
    }
    size_t o = (size_t)row * C;
    g_hw[o + lane] = a0;
    g_hw[o + lane + 32] = a1;
    g_res[o + lane] = r0 + bs_[lane];
    g_res[o + lane + 32] = r1 + bs_[lane + 32];
    float p = a0 * as_[lane] + a1 * as_[lane + 32];
    float q = a0 * ad_[lane] + a1 * ad_[lane + 32];
    #pragma unroll
    for (int off = 16; off; off >>= 1) {
        p += __shfl_xor_sync(0xffffffffu, p, off);
        q += __shfl_xor_sync(0xffffffffu, q, off);
    }
    if (lane == 0) { g_hs[row] = p; g_hd[row] = q; }
}

// ---------------- per-dst online-softmax aggregation ----------------
__global__ void k_agg(int layer, int act) {
    int d = blockIdx.x * 8 + (threadIdx.x >> 5);
    if (d >= N_NODES) return;
    int lane = threadIdx.x & 31;
    int beg = g_rowptr[d], end = g_rowptr[d + 1];
    float hdv = g_hd[d];
    const float* et = g_et + (size_t)layer * N_EDGES;
    float m = -CUDART_INF_F, s = 0.0f, acc0 = 0.0f, acc1 = 0.0f;
    for (int p = beg; p < end; p++) {
        int src = g_csr_src[p];
        float alpha = g_hs[src] + hdv + et[p];
        alpha = (alpha > 0.0f) ? alpha : 0.2f * alpha;   // leaky_relu 0.2
        float nm = fmaxf(m, alpha);
        float cold = __expf(m - nm);    // 0 on first iter (m = -inf)
        float pe = __expf(alpha - nm);
        const float* hv = g_hw + (size_t)src * C;
        float h0 = hv[lane], h1 = hv[lane + 32];
        s = s * cold + pe;
        acc0 = fmaf(pe, h0, acc0 * cold);
        acc1 = fmaf(pe, h1, acc1 * cold);
        m = nm;
    }
    float w = 1.0f / (s + 1e-16f);
    size_t o = (size_t)d * C;
    float o0 = acc0 * w + g_res[o + lane];
    float o1 = acc1 * w + g_res[o + lane + 32];
    if (act) {
        o0 = (o0 > 0.0f) ? o0 : 0.01f * o0;
        o1 = (o1 > 0.0f) ? o1 : 0.01f * o1;
    }
    g_feat[o + lane] = o0;
    g_feat[o + lane + 32] = o1;
}

// ---------------- pooling ----------------
__global__ void k_pool(const int* __restrict__ batch) {
    int idx = blockIdx.x * blockDim.x + threadIdx.x;
    if (idx >= N_NODES * C) return;
    int n = idx >> 6, c = idx & 63;
    float v = g_feat[idx];
    int g = batch[n];
    atomicMax(&g_gmax[g * C + c], fenc(v));
    atomicAdd(&g_gsum[g * C + c], v);
    if (c == 0) atomicAdd(&g_gcnt[g], 1);
}

// ---------------- final projection ----------------
__global__ void k_out(const float* __restrict__ Wout, const float* __restrict__ bout,
                      float* __restrict__ out) {
    int g = blockIdx.x;
    int t = threadIdx.x;  // 256 threads = D_OUT
    __shared__ float pooled[2 * C];
    if (t < C) {
        float mx = fdec(g_gmax[g * C + t]);
        if (!isfinite(mx)) mx = 0.0f;
        pooled[t] = (mx > 0.0f) ? mx : 0.01f * mx;
    } else if (t < 2 * C) {
        int c = t - C;
        float cnt = (float)max(g_gcnt[g], 1);
        float mn = g_gsum[g * C + c] / cnt;
        pooled[t] = (mn > 0.0f) ? mn : 0.01f * mn;
    }
    __syncthreads();
    float acc = bout[t];
    #pragma unroll
    for (int k = 0; k < 2 * C; k++)
        acc = fmaf(pooled[k], Wout[(size_t)k * D_OUT + t], acc);
    out[(size_t)g * D_OUT + t] = acc;
}

// ---------------- launch ----------------
extern "C" void kernel_launch(void* const* d_in, const int* in_sizes, int n_in,
                              void* d_out, int out_size) {
    const float* x      = (const float*)d_in[0];
    const float* eattr  = (const float*)d_in[1];
    const float* W0     = (const float*)d_in[2];
    const float* asrc0  = (const float*)d_in[3];
    const float* adst0  = (const float*)d_in[4];
    const float* We0    = (const float*)d_in[5];
    const float* ae0    = (const float*)d_in[6];
    const float* Wres0  = (const float*)d_in[7];
    const float* b0     = (const float*)d_in[8];
    const float* W      = (const float*)d_in[9];
    const float* asrc   = (const float*)d_in[10];
    const float* adst   = (const float*)d_in[11];
    const float* We     = (const float*)d_in[12];
    const float* ae     = (const float*)d_in[13];
    const float* Wres   = (const float*)d_in[14];
    const float* b      = (const float*)d_in[15];
    const float* Wout   = (const float*)d_in[16];
    const float* bout   = (const float*)d_in[17];
    const int*   eidx   = (const int*)d_in[18];
    const int*   batch  = (const int*)d_in[19];
    float* out = (float*)d_out;

    const int EB = (N_EDGES + 255) / 256;
    const int NB = (N_NODES + 7) / 8;

    k_init<<<(G_GR * C + 255) / 256, 256>>>(We0, ae0, We, ae);
    k_hist<<<EB, 256>>>(eidx);
    k_scan<<<1, 1024>>>();
    k_scatter<<<EB, 256>>>(eidx);
    k_et<<<EB, 256>>>(eattr);

    // layer 0 (F=30), leaky_relu 0.01 after
    k_gemm<F_IN, true><<<NB, 256>>>(x, W0, Wres0, asrc0, adst0, b0);
    k_agg<<<NB, 256>>>(0, 1);

    // layers 1..3 (F=64), activation after layers 1,2 only
    for (int i = 0; i < 3; i++) {
        k_gemm<C, false><<<NB, 256>>>(nullptr,
                                      W + (size_t)i * C * C,
                                      Wres + (size_t)i * C * C,
                                      asrc + (size_t)i * C,
                                      adst + (size_t)i * C,
                                      b + (size_t)i * C);
        k_agg<<<NB, 256>>>(i + 1, (i < 2) ? 1 : 0);
    }

    k_pool<<<(N_NODES * C + 255) / 256, 256>>>(batch);
    k_out<<<G_GR, D_OUT>>>(Wout, bout, out);
}